// round 3
// baseline (speedup 1.0000x reference)
#include <cuda_runtime.h>
#include <math.h>
#include <stdint.h>
#include <stddef.h>

#define FEAT    36
#define NNODES  24
#define NROUTES 48
#define CH      128
#define COUT    32
#define RH      128
#define BATCH   512
#define NSEQ    (BATCH * NROUTES)     /* 24576 */
#define G3      (3 * RH)              /* 384   */
#define NROWS   (NNODES * NSEQ)       /* 589824 */

typedef unsigned long long ull;

/* ---- packed f32x2 helpers (SASS FFMA2 path, only reachable via PTX) ---- */
__device__ __forceinline__ ull pack2s(float x) {
    ull r; asm("mov.b64 %0, {%1, %1};" : "=l"(r) : "f"(x)); return r;
}
__device__ __forceinline__ ull pack2(float x, float y) {
    ull r; asm("mov.b64 %0, {%1, %2};" : "=l"(r) : "f"(x), "f"(y)); return r;
}
__device__ __forceinline__ ull ffma2(ull a, ull b, ull c) {
    ull d; asm("fma.rn.f32x2 %0, %1, %2, %3;" : "=l"(d) : "l"(a), "l"(b), "l"(c)); return d;
}
__device__ __forceinline__ float2 unpk(ull v) {
    float lo, hi; asm("mov.b64 {%0, %1}, %2;" : "=f"(lo), "=f"(hi) : "l"(v));
    return make_float2(lo, hi);
}
__device__ __forceinline__ float sigm(float x) { return 1.f / (1.f + expf(-x)); }

/* scratch (no allocation allowed -> __device__ globals) */
__device__ float g_x32[(size_t)NROWS * COUT];   /* [t][n][32] node embeddings */
__device__ float g_last[(size_t)NSEQ * RH];     /* last GRU hidden per sequence */

/* duplicated-pair weights: [matrix 0..3][gate 0..2][k*128 + j] = (w,w)
   matrix: 0=wih0(32 rows) 1=whh0 2=wih1 3=whh1 */
__device__ ull g_whd[4][3][128 * 128];
__device__ ull g_w1d[FEAT * CH];       /* (w1,w1) pairs [i*128 + j] */
__device__ ull g_w2d[CH * COUT];       /* (w2,w2) pairs [k*32 + j2] */

/* ==================== prep: duplicate weights into packed pairs ==================== */
__global__ __launch_bounds__(256) void k_prep_gru(
    const float* __restrict__ wih0, const float* __restrict__ whh0,
    const float* __restrict__ wih1, const float* __restrict__ whh1)
{
    int idx = blockIdx.x * 256 + threadIdx.x;   /* over (32+128+128+128)*384 */
    if (idx >= 416 * 384) return;
    int k = idx / 384, c = idx - k * 384;
    int m, kk; const float* src;
    if      (k < 32)  { m = 0; kk = k;       src = wih0; }
    else if (k < 160) { m = 1; kk = k - 32;  src = whh0; }
    else if (k < 288) { m = 2; kk = k - 160; src = wih1; }
    else              { m = 3; kk = k - 288; src = whh1; }
    float v = src[kk * 384 + c];
    int g = c >> 7, j = c & 127;
    g_whd[m][g][kk * 128 + j] = pack2(v, v);
}

__global__ __launch_bounds__(256) void k_prep_cust(
    const float* __restrict__ w1, const float* __restrict__ w2)
{
    int idx = blockIdx.x * 256 + threadIdx.x;
    if (idx < FEAT * CH) {
        float v = w1[idx];
        g_w1d[idx] = pack2(v, v);
    }
    int i2 = idx - FEAT * CH;
    if (i2 >= 0 && i2 < CH * COUT) {
        float v = w2[i2];
        g_w2d[i2] = pack2(v, v);
    }
}

/* ==================== K1: customer MLP 36->128(tanh)->32(tanh) ==================== */
#define K1_ROWS 64
#define XT_ST   68
#define HT_ST   68

__global__ __launch_bounds__(256) void k_cust(
    const float* __restrict__ cust,           /* [NSEQ][NNODES*FEAT] */
    const float* __restrict__ b1, const float* __restrict__ b2)
{
    __shared__ __align__(16) float xT[FEAT * XT_ST];   /* [36][68] transposed inputs  */
    __shared__ __align__(16) float hT[CH * HT_ST];     /* [128][68] transposed hidden */
    const int tid = threadIdx.x;
    const long long row0 = (long long)blockIdx.x * K1_ROWS;   /* row = t*NSEQ + n */

    #pragma unroll
    for (int rep = 0; rep < K1_ROWS * FEAT / 256; rep++) {
        int e = tid + rep * 256;
        int s = e / FEAT, f = e - s * FEAT;
        long long row = row0 + s;
        int t = (int)(row / NSEQ);
        int n = (int)(row - (long long)t * NSEQ);
        xT[f * XT_ST + s] = cust[(size_t)n * (NNODES * FEAT) + t * FEAT + f];
    }
    __syncthreads();

    /* phase 1: hT[j][s] = tanh(b1[j] + sum_i xT[i][s] * w1[i][j]) */
    {
        const int j  = tid & 127;
        const int s0 = (tid >> 7) * 32;       /* two halves of 32 rows */
        ull a[16];
        ull bb = pack2s(b1[j]);
        #pragma unroll
        for (int u = 0; u < 16; u++) a[u] = bb;
        #pragma unroll 4
        for (int i = 0; i < FEAT; i++) {
            ull w = g_w1d[i * CH + j];
            const ulonglong2* xp = (const ulonglong2*)(xT + i * XT_ST + s0);
            #pragma unroll
            for (int q = 0; q < 8; q++) {
                ulonglong2 v = xp[q];
                a[2 * q]     = ffma2(w, v.x, a[2 * q]);
                a[2 * q + 1] = ffma2(w, v.y, a[2 * q + 1]);
            }
        }
        float* hp = hT + j * HT_ST + s0;
        #pragma unroll
        for (int q = 0; q < 8; q++) {
            float2 p0 = unpk(a[2 * q]), p1 = unpk(a[2 * q + 1]);
            float4 o = make_float4(tanhf(p0.x), tanhf(p0.y), tanhf(p1.x), tanhf(p1.y));
            *(float4*)(hp + 4 * q) = o;
        }
    }
    __syncthreads();

    /* phase 2: out[s][j2] = tanh(b2[j2] + sum_k hT[k][s] * w2[k][j2]) */
    {
        const int j2 = tid & 31;
        const int s0 = (tid >> 5) * 8;        /* 8 groups of 8 rows */
        ull a[4];
        ull bb = pack2s(b2[j2]);
        #pragma unroll
        for (int u = 0; u < 4; u++) a[u] = bb;
        #pragma unroll 4
        for (int k = 0; k < CH; k++) {
            ull w = g_w2d[k * COUT + j2];
            const ulonglong2* hp = (const ulonglong2*)(hT + k * HT_ST + s0);
            ulonglong2 v0 = hp[0], v1 = hp[1];
            a[0] = ffma2(w, v0.x, a[0]);
            a[1] = ffma2(w, v0.y, a[1]);
            a[2] = ffma2(w, v1.x, a[2]);
            a[3] = ffma2(w, v1.y, a[3]);
        }
        size_t base = (size_t)(row0 + s0) * COUT + j2;
        #pragma unroll
        for (int q = 0; q < 4; q++) {
            float2 p = unpk(a[q]);
            g_x32[base + (size_t)(2 * q) * COUT]     = tanhf(p.x);
            g_x32[base + (size_t)(2 * q + 1) * COUT] = tanhf(p.y);
        }
    }
}

/* ==================== K2: fused 2-layer GRU over 24 steps ==================== */
#define STILE 64          /* sequences per block */
#define PAD   68          /* shared row stride: 16B-aligned rows for LDS.128 */
#define K2_SMEM ((2 * 128 * PAD + 32 * PAD) * 4)   /* 78336 bytes */

/* One GRU cell step for 16 sequences (2 blocks of 8) handled by this thread.
   All inner-loop shared reads are warp-broadcast (all lanes same address). */
template <int IN>
__device__ __forceinline__ void gru_cell(
    const ull* __restrict__ Wih,   /* g_whd[m][0]; gates at +16384, +32768 */
    const ull* __restrict__ Whh,
    const float* __restrict__ bih, const float* __restrict__ bhh,
    const float* xbuf,   /* shared [IN][PAD]  (transposed: [feature][seq]) */
    const float* hbuf,   /* shared [128][PAD] */
    int j, int sA, ull* hn)
{
    ull ar[8], az[8], ai[8], ah[8];
    {
        ull br2 = pack2s(bih[j] + bhh[j]);
        ull bz2 = pack2s(bih[128 + j] + bhh[128 + j]);
        ull bi2 = pack2s(bih[256 + j]);
        ull bh2 = pack2s(bhh[256 + j]);
        #pragma unroll
        for (int u = 0; u < 8; u++) { ar[u] = br2; az[u] = bz2; ai[u] = bi2; ah[u] = bh2; }
    }

    /* input-to-hidden gates */
    #pragma unroll 4
    for (int i = 0; i < IN; i++) {
        const int o = i * 128 + j;
        ull wr2 = Wih[o];
        ull wz2 = Wih[16384 + o];
        ull wn2 = Wih[32768 + o];
        const ulonglong2* xa = (const ulonglong2*)(xbuf + i * PAD + sA);
        ulonglong2 p0 = xa[0], p1 = xa[1];
        ar[0] = ffma2(wr2, p0.x, ar[0]); az[0] = ffma2(wz2, p0.x, az[0]); ai[0] = ffma2(wn2, p0.x, ai[0]);
        ar[1] = ffma2(wr2, p0.y, ar[1]); az[1] = ffma2(wz2, p0.y, az[1]); ai[1] = ffma2(wn2, p0.y, ai[1]);
        ar[2] = ffma2(wr2, p1.x, ar[2]); az[2] = ffma2(wz2, p1.x, az[2]); ai[2] = ffma2(wn2, p1.x, ai[2]);
        ar[3] = ffma2(wr2, p1.y, ar[3]); az[3] = ffma2(wz2, p1.y, az[3]); ai[3] = ffma2(wn2, p1.y, ai[3]);
        const ulonglong2* xb = (const ulonglong2*)(xbuf + i * PAD + sA + 32);
        ulonglong2 q0 = xb[0], q1 = xb[1];
        ar[4] = ffma2(wr2, q0.x, ar[4]); az[4] = ffma2(wz2, q0.x, az[4]); ai[4] = ffma2(wn2, q0.x, ai[4]);
        ar[5] = ffma2(wr2, q0.y, ar[5]); az[5] = ffma2(wz2, q0.y, az[5]); ai[5] = ffma2(wn2, q0.y, ai[5]);
        ar[6] = ffma2(wr2, q1.x, ar[6]); az[6] = ffma2(wz2, q1.x, az[6]); ai[6] = ffma2(wn2, q1.x, ai[6]);
        ar[7] = ffma2(wr2, q1.y, ar[7]); az[7] = ffma2(wz2, q1.y, az[7]); ai[7] = ffma2(wn2, q1.y, ai[7]);
    }
    /* hidden-to-hidden gates */
    #pragma unroll 4
    for (int k = 0; k < RH; k++) {
        const int o = k * 128 + j;
        ull wr2 = Whh[o];
        ull wz2 = Whh[16384 + o];
        ull wn2 = Whh[32768 + o];
        const ulonglong2* ha = (const ulonglong2*)(hbuf + k * PAD + sA);
        ulonglong2 p0 = ha[0], p1 = ha[1];
        ar[0] = ffma2(wr2, p0.x, ar[0]); az[0] = ffma2(wz2, p0.x, az[0]); ah[0] = ffma2(wn2, p0.x, ah[0]);
        ar[1] = ffma2(wr2, p0.y, ar[1]); az[1] = ffma2(wz2, p0.y, az[1]); ah[1] = ffma2(wn2, p0.y, ah[1]);
        ar[2] = ffma2(wr2, p1.x, ar[2]); az[2] = ffma2(wz2, p1.x, az[2]); ah[2] = ffma2(wn2, p1.x, ah[2]);
        ar[3] = ffma2(wr2, p1.y, ar[3]); az[3] = ffma2(wz2, p1.y, az[3]); ah[3] = ffma2(wn2, p1.y, ah[3]);
        const ulonglong2* hb = (const ulonglong2*)(hbuf + k * PAD + sA + 32);
        ulonglong2 q0 = hb[0], q1 = hb[1];
        ar[4] = ffma2(wr2, q0.x, ar[4]); az[4] = ffma2(wz2, q0.x, az[4]); ah[4] = ffma2(wn2, q0.x, ah[4]);
        ar[5] = ffma2(wr2, q0.y, ar[5]); az[5] = ffma2(wz2, q0.y, az[5]); ah[5] = ffma2(wn2, q0.y, ah[5]);
        ar[6] = ffma2(wr2, q1.x, ar[6]); az[6] = ffma2(wz2, q1.x, az[6]); ah[6] = ffma2(wn2, q1.x, ah[6]);
        ar[7] = ffma2(wr2, q1.y, ar[7]); az[7] = ffma2(wz2, q1.y, az[7]); ah[7] = ffma2(wn2, q1.y, ah[7]);
    }
    /* gate nonlinearities + state update (r,z,n order as in reference) */
    #pragma unroll
    for (int u = 0; u < 8; u++) {
        int s = sA + ((u < 4) ? 2 * u : 32 + 2 * (u - 4));
        float2 hold = *(const float2*)(hbuf + j * PAD + s);
        float2 R = unpk(ar[u]), Z = unpk(az[u]), I = unpk(ai[u]), H = unpk(ah[u]);
        float r0 = sigm(R.x), z0 = sigm(Z.x);
        float n0 = tanhf(I.x + r0 * H.x);
        float o0 = (1.f - z0) * n0 + z0 * hold.x;
        float r1 = sigm(R.y), z1 = sigm(Z.y);
        float n1 = tanhf(I.y + r1 * H.y);
        float o1 = (1.f - z1) * n1 + z1 * hold.y;
        hn[u] = pack2(o0, o1);
    }
}

__global__ __launch_bounds__(512, 1) void k_gru(
    const float* __restrict__ bih0, const float* __restrict__ bhh0,
    const float* __restrict__ bih1, const float* __restrict__ bhh1)
{
    extern __shared__ float smem[];
    float* h0buf = smem;                   /* [128][PAD] layer-0 state / layer-1 input */
    float* h1buf = smem + 128 * PAD;       /* [128][PAD] layer-1 state */
    float* xt    = smem + 2 * 128 * PAD;   /* [32][PAD]  step input (transposed) */
    const int tid = threadIdx.x;
    const int j   = tid & 127;
    const int sA  = (tid >> 7) * 8;        /* first 8-seq block; second is +32 */
    const int nbase = blockIdx.x * STILE;

    for (int i = tid; i < 2 * 128 * PAD; i += 512) smem[i] = 0.f;  /* h0 = h1 = 0 */

    const ull* Wih0 = &g_whd[0][0][0];
    const ull* Whh0 = &g_whd[1][0][0];
    const ull* Wih1 = &g_whd[2][0][0];
    const ull* Whh1 = &g_whd[3][0][0];

    ull hn[8];

    for (int t = 0; t < NNODES; t++) {
        /* load & transpose this step's inputs: 64 seqs x 32 feats */
        const float* src = g_x32 + ((size_t)t * NSEQ + nbase) * COUT;
        #pragma unroll
        for (int rep = 0; rep < 4; rep++) {
            int e = tid + rep * 512;
            xt[(e & 31) * PAD + (e >> 5)] = src[e];
        }
        __syncthreads();   /* also orders zero-init on t==0 and h1 stores of t-1 */

        gru_cell<COUT>(Wih0, Whh0, bih0, bhh0, xt, h0buf, j, sA, hn);
        __syncthreads();
        #pragma unroll
        for (int u = 0; u < 8; u++) {
            int s = sA + ((u < 4) ? 2 * u : 32 + 2 * (u - 4));
            *(ull*)(h0buf + j * PAD + s) = hn[u];
        }
        __syncthreads();

        gru_cell<RH>(Wih1, Whh1, bih1, bhh1, h0buf, h1buf, j, sA, hn);
        __syncthreads();
        #pragma unroll
        for (int u = 0; u < 8; u++) {
            int s = sA + ((u < 4) ? 2 * u : 32 + 2 * (u - 4));
            *(ull*)(h1buf + j * PAD + s) = hn[u];
        }
    }

    /* hn holds the final (t = 23) layer-1 state for this thread's cells */
    #pragma unroll
    for (int u = 0; u < 8; u++) {
        int s = sA + ((u < 4) ? 2 * u : 32 + 2 * (u - 4));
        float2 v = unpk(hn[u]);
        g_last[(size_t)(nbase + s) * RH + j]     = v.x;
        g_last[(size_t)(nbase + s + 1) * RH + j] = v.y;
    }
}

/* ==================== K3: mean over routes + head MLP ==================== */
__global__ __launch_bounds__(128) void k_final(
    const float* __restrict__ cand,
    const float* __restrict__ cand_w, const float* __restrict__ cand_b,
    const float* __restrict__ fc1w, const float* __restrict__ fc1b,
    const float* __restrict__ fc2w, const float* __restrict__ fc2b,
    const float* __restrict__ fc3w, const float* __restrict__ fc3b,
    float* __restrict__ out)
{
    __shared__ float xr[RH + 64];   /* concat [x_r(128), x_c(64)] */
    __shared__ float h[128];
    __shared__ float red[128];
    const int b = blockIdx.x, tid = threadIdx.x;

    /* x_r: mean over 48 routes of last hidden */
    {
        const float* base = g_last + (size_t)b * NROUTES * RH;
        float acc = 0.f;
        #pragma unroll 8
        for (int r = 0; r < NROUTES; r++) acc += base[r * RH + tid];
        xr[tid] = acc * (1.f / NROUTES);
    }
    /* x_c = candidates @ cand_w + cand_b (no activation) */
    if (tid < 64) {
        float a = cand_b[tid];
        #pragma unroll 8
        for (int i = 0; i < 2 * FEAT; i++)
            a += cand[b * 2 * FEAT + i] * cand_w[i * 64 + tid];
        xr[RH + tid] = a;
    }
    __syncthreads();

    {
        float a = fc1b[tid];
        #pragma unroll 8
        for (int i = 0; i < RH + 64; i++) a += xr[i] * fc1w[i * 128 + tid];
        h[tid] = tanhf(a);
    }
    __syncthreads();
    {
        float a = fc2b[tid];
        #pragma unroll 8
        for (int i = 0; i < 128; i++) a += h[i] * fc2w[i * 128 + tid];
        red[tid] = tanhf(a) * fc3w[tid];
    }
    __syncthreads();
    for (int s = 64; s > 0; s >>= 1) {
        if (tid < s) red[tid] += red[tid + s];
        __syncthreads();
    }
    if (tid == 0) out[b] = red[0] + fc3b[0];
}

/* ==================== launch ==================== */
extern "C" void kernel_launch(void* const* d_in, const int* in_sizes, int n_in,
                              void* d_out, int out_size)
{
    const float* candidates = (const float*)d_in[0];
    const float* customers  = (const float*)d_in[1];
    const float* cust_w1 = (const float*)d_in[2];
    const float* cust_b1 = (const float*)d_in[3];
    const float* cust_w2 = (const float*)d_in[4];
    const float* cust_b2 = (const float*)d_in[5];
    const float* wih0 = (const float*)d_in[6];
    const float* whh0 = (const float*)d_in[7];
    const float* bih0 = (const float*)d_in[8];
    const float* bhh0 = (const float*)d_in[9];
    const float* wih1 = (const float*)d_in[10];
    const float* whh1 = (const float*)d_in[11];
    const float* bih1 = (const float*)d_in[12];
    const float* bhh1 = (const float*)d_in[13];
    const float* cand_w = (const float*)d_in[14];
    const float* cand_b = (const float*)d_in[15];
    const float* fc1w = (const float*)d_in[16];
    const float* fc1b = (const float*)d_in[17];
    const float* fc2w = (const float*)d_in[18];
    const float* fc2b = (const float*)d_in[19];
    const float* fc3w = (const float*)d_in[20];
    const float* fc3b = (const float*)d_in[21];

    cudaFuncSetAttribute(k_gru, cudaFuncAttributeMaxDynamicSharedMemorySize, K2_SMEM);

    k_prep_gru<<<(416 * 384 + 255) / 256, 256>>>(wih0, whh0, wih1, whh1);
    k_prep_cust<<<(FEAT * CH + CH * COUT + 255) / 256, 256>>>(cust_w1, cust_w2);
    k_cust<<<NROWS / K1_ROWS, 256>>>(customers, cust_b1, cust_b2);
    k_gru<<<NSEQ / STILE, 512, K2_SMEM>>>(bih0, bhh0, bih1, bhh1);
    k_final<<<BATCH, 128>>>(candidates, cand_w, cand_b,
                            fc1w, fc1b, fc2w, fc2b, fc3w, fc3b,
                            (float*)d_out);
}

// round 4
// speedup vs baseline: 1.1733x; 1.1733x over previous
#include <cuda_runtime.h>
#include <math.h>
#include <stdint.h>
#include <stddef.h>

#define FEAT    36
#define NNODES  24
#define NROUTES 48
#define CH      128
#define COUT    32
#define RH      128
#define BATCH   512
#define NSEQ    (BATCH * NROUTES)     /* 24576 */
#define G3      (3 * RH)              /* 384   */
#define NROWS   (NNODES * NSEQ)       /* 589824 */

typedef unsigned long long ull;

/* ---- packed f32x2 helpers (SASS FFMA2 path, only reachable via PTX) ---- */
__device__ __forceinline__ ull pack2s(float x) {
    ull r; asm("mov.b64 %0, {%1, %1};" : "=l"(r) : "f"(x)); return r;
}
__device__ __forceinline__ ull pack2(float x, float y) {
    ull r; asm("mov.b64 %0, {%1, %2};" : "=l"(r) : "f"(x), "f"(y)); return r;
}
__device__ __forceinline__ ull ffma2(ull a, ull b, ull c) {
    ull d; asm("fma.rn.f32x2 %0, %1, %2, %3;" : "=l"(d) : "l"(a), "l"(b), "l"(c)); return d;
}
__device__ __forceinline__ float2 unpk(ull v) {
    float lo, hi; asm("mov.b64 {%0, %1}, %2;" : "=f"(lo), "=f"(hi) : "l"(v));
    return make_float2(lo, hi);
}
__device__ __forceinline__ float sigm(float x) { return 1.f / (1.f + expf(-x)); }

__device__ __forceinline__ void cp16(float* dst, const float4* src) {
    unsigned s = (unsigned)__cvta_generic_to_shared(dst);
    asm volatile("cp.async.ca.shared.global [%0], [%1], 16;" :: "r"(s), "l"(src));
}

/* scratch (no allocation allowed -> __device__ globals) */
__device__ float g_x32[(size_t)NROWS * COUT];   /* [t][n][32] node embeddings */
__device__ float g_last[(size_t)NSEQ * RH];     /* last GRU hidden per sequence */

/* GRU weights concatenated in streaming order: rows 0-31 wih0, 32-159 whh0,
   160-287 wih1, 288-415 whh1; each row = 384 cols (r|z|n gates) */
#define KCH 32
#define CHUNK_FLOATS (KCH * G3)    /* 12288 floats = 49152 B */
#define NCHUNK 13
__device__ float g_wcat[NCHUNK * CHUNK_FLOATS];

__device__ ull g_w1d[FEAT * CH];   /* (w1,w1) pairs for k_cust */
__device__ ull g_w2d[CH * COUT];

/* ==================== prep kernels ==================== */
__global__ __launch_bounds__(256) void k_prep_gru(
    const float* __restrict__ wih0, const float* __restrict__ whh0,
    const float* __restrict__ wih1, const float* __restrict__ whh1)
{
    int idx = blockIdx.x * 256 + threadIdx.x;   /* over 416*384 */
    if (idx >= 416 * 384) return;
    int k = idx / 384, c = idx - k * 384;
    int kk; const float* src;
    if      (k < 32)  { kk = k;       src = wih0; }
    else if (k < 160) { kk = k - 32;  src = whh0; }
    else if (k < 288) { kk = k - 160; src = wih1; }
    else              { kk = k - 288; src = whh1; }
    g_wcat[idx] = src[kk * 384 + c];
}

__global__ __launch_bounds__(256) void k_prep_cust(
    const float* __restrict__ w1, const float* __restrict__ w2)
{
    int idx = blockIdx.x * 256 + threadIdx.x;
    if (idx < FEAT * CH) {
        float v = w1[idx];
        g_w1d[idx] = pack2(v, v);
    }
    int i2 = idx - FEAT * CH;
    if (i2 >= 0 && i2 < CH * COUT) {
        float v = w2[i2];
        g_w2d[i2] = pack2(v, v);
    }
}

/* ==================== K1: customer MLP 36->128(tanh)->32(tanh) ==================== */
#define K1_ROWS 64
#define XT_ST   68
#define HT_ST   68

__global__ __launch_bounds__(256) void k_cust(
    const float* __restrict__ cust,           /* [NSEQ][NNODES*FEAT] */
    const float* __restrict__ b1, const float* __restrict__ b2)
{
    __shared__ __align__(16) float xT[FEAT * XT_ST];
    __shared__ __align__(16) float hT[CH * HT_ST];
    const int tid = threadIdx.x;
    const long long row0 = (long long)blockIdx.x * K1_ROWS;   /* row = t*NSEQ + n */

    #pragma unroll
    for (int rep = 0; rep < K1_ROWS * FEAT / 256; rep++) {
        int e = tid + rep * 256;
        int s = e / FEAT, f = e - s * FEAT;
        long long row = row0 + s;
        int t = (int)(row / NSEQ);
        int n = (int)(row - (long long)t * NSEQ);
        xT[f * XT_ST + s] = cust[(size_t)n * (NNODES * FEAT) + t * FEAT + f];
    }
    __syncthreads();

    /* phase 1 */
    {
        const int j  = tid & 127;
        const int s0 = (tid >> 7) * 32;
        ull a[16];
        ull bb = pack2s(b1[j]);
        #pragma unroll
        for (int u = 0; u < 16; u++) a[u] = bb;
        #pragma unroll 4
        for (int i = 0; i < FEAT; i++) {
            ull w = g_w1d[i * CH + j];
            const ulonglong2* xp = (const ulonglong2*)(xT + i * XT_ST + s0);
            #pragma unroll
            for (int q = 0; q < 8; q++) {
                ulonglong2 v = xp[q];
                a[2 * q]     = ffma2(w, v.x, a[2 * q]);
                a[2 * q + 1] = ffma2(w, v.y, a[2 * q + 1]);
            }
        }
        float* hp = hT + j * HT_ST + s0;
        #pragma unroll
        for (int q = 0; q < 8; q++) {
            float2 p0 = unpk(a[2 * q]), p1 = unpk(a[2 * q + 1]);
            float4 o = make_float4(tanhf(p0.x), tanhf(p0.y), tanhf(p1.x), tanhf(p1.y));
            *(float4*)(hp + 4 * q) = o;
        }
    }
    __syncthreads();

    /* phase 2 */
    {
        const int j2 = tid & 31;
        const int s0 = (tid >> 5) * 8;
        ull a[4];
        ull bb = pack2s(b2[j2]);
        #pragma unroll
        for (int u = 0; u < 4; u++) a[u] = bb;
        #pragma unroll 4
        for (int k = 0; k < CH; k++) {
            ull w = g_w2d[k * COUT + j2];
            const ulonglong2* hp = (const ulonglong2*)(hT + k * HT_ST + s0);
            ulonglong2 v0 = hp[0], v1 = hp[1];
            a[0] = ffma2(w, v0.x, a[0]);
            a[1] = ffma2(w, v0.y, a[1]);
            a[2] = ffma2(w, v1.x, a[2]);
            a[3] = ffma2(w, v1.y, a[3]);
        }
        size_t base = (size_t)(row0 + s0) * COUT + j2;
        #pragma unroll
        for (int q = 0; q < 4; q++) {
            float2 p = unpk(a[q]);
            g_x32[base + (size_t)(2 * q) * COUT]     = tanhf(p.x);
            g_x32[base + (size_t)(2 * q + 1) * COUT] = tanhf(p.y);
        }
    }
}

/* ==================== K2: fused 2-layer GRU, cp.async-staged weights ==================== */
#define STILE 64
#define PAD   68
#define K2_SMEM ((288 * PAD + 2 * CHUNK_FLOATS) * 4)   /* 78336 + 98304 = 176640 B */

/* accumulate one 32-row weight chunk (smem) against one smem activation tile */
__device__ __forceinline__ void compute_chunk(
    const float* __restrict__ ws,    /* smem [32][384] weight chunk */
    const float* __restrict__ src,   /* smem activations [32+][PAD], row-offset applied */
    int j, int sA,
    ull* __restrict__ ar, ull* __restrict__ az, ull* __restrict__ an)
{
    #pragma unroll 8
    for (int kl = 0; kl < KCH; kl++) {
        const float* wp = ws + kl * G3 + j;
        ull wr2 = pack2s(wp[0]);
        ull wz2 = pack2s(wp[128]);
        ull wn2 = pack2s(wp[256]);
        const ulonglong2* pa = (const ulonglong2*)(src + kl * PAD + sA);
        ulonglong2 p0 = pa[0], p1 = pa[1];
        ar[0] = ffma2(wr2, p0.x, ar[0]); az[0] = ffma2(wz2, p0.x, az[0]); an[0] = ffma2(wn2, p0.x, an[0]);
        ar[1] = ffma2(wr2, p0.y, ar[1]); az[1] = ffma2(wz2, p0.y, az[1]); an[1] = ffma2(wn2, p0.y, an[1]);
        ar[2] = ffma2(wr2, p1.x, ar[2]); az[2] = ffma2(wz2, p1.x, az[2]); an[2] = ffma2(wn2, p1.x, an[2]);
        ar[3] = ffma2(wr2, p1.y, ar[3]); az[3] = ffma2(wz2, p1.y, az[3]); an[3] = ffma2(wn2, p1.y, an[3]);
        const ulonglong2* pb = (const ulonglong2*)(src + kl * PAD + sA + 32);
        ulonglong2 q0 = pb[0], q1 = pb[1];
        ar[4] = ffma2(wr2, q0.x, ar[4]); az[4] = ffma2(wz2, q0.x, az[4]); an[4] = ffma2(wn2, q0.x, an[4]);
        ar[5] = ffma2(wr2, q0.y, ar[5]); az[5] = ffma2(wz2, q0.y, az[5]); an[5] = ffma2(wn2, q0.y, an[5]);
        ar[6] = ffma2(wr2, q1.x, ar[6]); az[6] = ffma2(wz2, q1.x, az[6]); an[6] = ffma2(wn2, q1.x, an[6]);
        ar[7] = ffma2(wr2, q1.y, ar[7]); az[7] = ffma2(wz2, q1.y, az[7]); an[7] = ffma2(wn2, q1.y, an[7]);
    }
}

__device__ __forceinline__ void issue_chunk(int cid, float* slot, int tid)
{
    const float4* g = (const float4*)(g_wcat + (size_t)cid * CHUNK_FLOATS);
    float4* d = (float4*)slot;
    #pragma unroll
    for (int i = 0; i < 6; i++)
        cp16((float*)(d + tid + i * 512), g + tid + i * 512);
    asm volatile("cp.async.commit_group;");
}

__global__ __launch_bounds__(512, 1) void k_gru(
    const float* __restrict__ bih0, const float* __restrict__ bhh0,
    const float* __restrict__ bih1, const float* __restrict__ bhh1)
{
    extern __shared__ __align__(16) float smem[];
    float* h0buf = smem;                   /* [128][PAD] */
    float* h1buf = smem + 128 * PAD;       /* [128][PAD] */
    float* xt    = smem + 256 * PAD;       /* [32][PAD]  */
    float* wring = smem + 288 * PAD;       /* [2][CHUNK_FLOATS] */
    const int tid = threadIdx.x;
    const int j   = tid & 127;
    const int sA  = (tid >> 7) * 8;        /* first 8-seq pair-block; second is +32 */
    const int nbase = blockIdx.x * STILE;

    for (int i = tid; i < 256 * PAD; i += 512) smem[i] = 0.f;  /* h0 = h1 = 0 */

    /* packed biases */
    const ull br0 = pack2s(bih0[j] + bhh0[j]);
    const ull bz0 = pack2s(bih0[128 + j] + bhh0[128 + j]);
    const ull bi0 = pack2s(bih0[256 + j]);
    const ull bh0 = pack2s(bhh0[256 + j]);
    const ull br1 = pack2s(bih1[j] + bhh1[j]);
    const ull bz1 = pack2s(bih1[128 + j] + bhh1[128 + j]);
    const ull bi1 = pack2s(bih1[256 + j]);
    const ull bh1 = pack2s(bhh1[256 + j]);

    /* ring prologue: chunks 0 and 1 in flight */
    issue_chunk(0, wring, tid);
    issue_chunk(1, wring + CHUNK_FLOATS, tid);
    int cc = 0;                            /* absolute chunk counter */

    ull ar[8], az[8], ai[8], ah[8];
    ull hn[8];

#define RING_STEP(SRC, TGT)                                                     \
    do {                                                                        \
        asm volatile("cp.async.wait_group 1;");                                 \
        __syncthreads();                                                        \
        compute_chunk(wring + (cc & 1) * CHUNK_FLOATS, (SRC), j, sA, ar, az, (TGT)); \
        __syncthreads();                                                        \
        { int nid = cc + 2;                                                     \
          issue_chunk(nid % NCHUNK, wring + (nid & 1) * CHUNK_FLOATS, tid); }   \
        cc++;                                                                   \
    } while (0)

    for (int t = 0; t < NNODES; t++) {
        /* load & transpose this step's inputs: 64 seqs x 32 feats */
        const float* src = g_x32 + ((size_t)t * NSEQ + nbase) * COUT;
        #pragma unroll
        for (int rep = 0; rep < 4; rep++) {
            int e = tid + rep * 512;
            xt[(e & 31) * PAD + (e >> 5)] = src[e];
        }
        /* xt stores ordered by RING_STEP's pre-compute barrier */

        /* ---- cell 0 ---- */
        #pragma unroll
        for (int u = 0; u < 8; u++) { ar[u] = br0; az[u] = bz0; ai[u] = bi0; ah[u] = bh0; }
        RING_STEP(xt, ai);                              /* chunk 0: wih0 @ x_t   */
        #pragma unroll 1
        for (int q = 0; q < 4; q++)
            RING_STEP(h0buf + q * 32 * PAD, ah);        /* chunks 1-4: whh0 @ h0 */
        /* epilogue 0 (reads old h0) */
        #pragma unroll
        for (int u = 0; u < 8; u++) {
            int s = sA + ((u < 4) ? 2 * u : 32 + 2 * (u - 4));
            float2 hold = *(const float2*)(h0buf + j * PAD + s);
            float2 R = unpk(ar[u]), Z = unpk(az[u]), I = unpk(ai[u]), H = unpk(ah[u]);
            float r0 = sigm(R.x), z0 = sigm(Z.x);
            float n0 = tanhf(I.x + r0 * H.x);
            float o0 = (1.f - z0) * n0 + z0 * hold.x;
            float r1 = sigm(R.y), z1 = sigm(Z.y);
            float n1 = tanhf(I.y + r1 * H.y);
            float o1 = (1.f - z1) * n1 + z1 * hold.y;
            hn[u] = pack2(o0, o1);
        }
        __syncthreads();
        #pragma unroll
        for (int u = 0; u < 8; u++) {
            int s = sA + ((u < 4) ? 2 * u : 32 + 2 * (u - 4));
            *(ull*)(h0buf + j * PAD + s) = hn[u];
        }
        /* h0 stores ordered by next RING_STEP barrier */

        /* ---- cell 1 ---- */
        #pragma unroll
        for (int u = 0; u < 8; u++) { ar[u] = br1; az[u] = bz1; ai[u] = bi1; ah[u] = bh1; }
        #pragma unroll 1
        for (int q = 0; q < 4; q++)
            RING_STEP(h0buf + q * 32 * PAD, ai);        /* chunks 5-8: wih1 @ h0_new */
        #pragma unroll 1
        for (int q = 0; q < 4; q++)
            RING_STEP(h1buf + q * 32 * PAD, ah);        /* chunks 9-12: whh1 @ h1 */
        /* epilogue 1 (reads old h1) */
        #pragma unroll
        for (int u = 0; u < 8; u++) {
            int s = sA + ((u < 4) ? 2 * u : 32 + 2 * (u - 4));
            float2 hold = *(const float2*)(h1buf + j * PAD + s);
            float2 R = unpk(ar[u]), Z = unpk(az[u]), I = unpk(ai[u]), H = unpk(ah[u]);
            float r0 = sigm(R.x), z0 = sigm(Z.x);
            float n0 = tanhf(I.x + r0 * H.x);
            float o0 = (1.f - z0) * n0 + z0 * hold.x;
            float r1 = sigm(R.y), z1 = sigm(Z.y);
            float n1 = tanhf(I.y + r1 * H.y);
            float o1 = (1.f - z1) * n1 + z1 * hold.y;
            hn[u] = pack2(o0, o1);
        }
        __syncthreads();
        #pragma unroll
        for (int u = 0; u < 8; u++) {
            int s = sA + ((u < 4) ? 2 * u : 32 + 2 * (u - 4));
            *(ull*)(h1buf + j * PAD + s) = hn[u];
        }
        /* h1/xt reuse ordered by next step's RING_STEP barrier */
    }
#undef RING_STEP

    /* hn holds the final (t = 23) layer-1 state for this thread's cells */
    #pragma unroll
    for (int u = 0; u < 8; u++) {
        int s = sA + ((u < 4) ? 2 * u : 32 + 2 * (u - 4));
        float2 v = unpk(hn[u]);
        g_last[(size_t)(nbase + s) * RH + j]     = v.x;
        g_last[(size_t)(nbase + s + 1) * RH + j] = v.y;
    }
}

/* ==================== K3: mean over routes + head MLP ==================== */
__global__ __launch_bounds__(128) void k_final(
    const float* __restrict__ cand,
    const float* __restrict__ cand_w, const float* __restrict__ cand_b,
    const float* __restrict__ fc1w, const float* __restrict__ fc1b,
    const float* __restrict__ fc2w, const float* __restrict__ fc2b,
    const float* __restrict__ fc3w, const float* __restrict__ fc3b,
    float* __restrict__ out)
{
    __shared__ float xr[RH + 64];
    __shared__ float h[128];
    __shared__ float red[128];
    const int b = blockIdx.x, tid = threadIdx.x;

    {
        const float* base = g_last + (size_t)b * NROUTES * RH;
        float acc = 0.f;
        #pragma unroll 8
        for (int r = 0; r < NROUTES; r++) acc += base[r * RH + tid];
        xr[tid] = acc * (1.f / NROUTES);
    }
    if (tid < 64) {
        float a = cand_b[tid];
        #pragma unroll 8
        for (int i = 0; i < 2 * FEAT; i++)
            a += cand[b * 2 * FEAT + i] * cand_w[i * 64 + tid];
        xr[RH + tid] = a;
    }
    __syncthreads();

    {
        float a = fc1b[tid];
        #pragma unroll 8
        for (int i = 0; i < RH + 64; i++) a += xr[i] * fc1w[i * 128 + tid];
        h[tid] = tanhf(a);
    }
    __syncthreads();
    {
        float a = fc2b[tid];
        #pragma unroll 8
        for (int i = 0; i < 128; i++) a += h[i] * fc2w[i * 128 + tid];
        red[tid] = tanhf(a) * fc3w[tid];
    }
    __syncthreads();
    for (int s = 64; s > 0; s >>= 1) {
        if (tid < s) red[tid] += red[tid + s];
        __syncthreads();
    }
    if (tid == 0) out[b] = red[0] + fc3b[0];
}

/* ==================== launch ==================== */
extern "C" void kernel_launch(void* const* d_in, const int* in_sizes, int n_in,
                              void* d_out, int out_size)
{
    const float* candidates = (const float*)d_in[0];
    const float* customers  = (const float*)d_in[1];
    const float* cust_w1 = (const float*)d_in[2];
    const float* cust_b1 = (const float*)d_in[3];
    const float* cust_w2 = (const float*)d_in[4];
    const float* cust_b2 = (const float*)d_in[5];
    const float* wih0 = (const float*)d_in[6];
    const float* whh0 = (const float*)d_in[7];
    const float* bih0 = (const float*)d_in[8];
    const float* bhh0 = (const float*)d_in[9];
    const float* wih1 = (const float*)d_in[10];
    const float* whh1 = (const float*)d_in[11];
    const float* bih1 = (const float*)d_in[12];
    const float* bhh1 = (const float*)d_in[13];
    const float* cand_w = (const float*)d_in[14];
    const float* cand_b = (const float*)d_in[15];
    const float* fc1w = (const float*)d_in[16];
    const float* fc1b = (const float*)d_in[17];
    const float* fc2w = (const float*)d_in[18];
    const float* fc2b = (const float*)d_in[19];
    const float* fc3w = (const float*)d_in[20];
    const float* fc3b = (const float*)d_in[21];

    cudaFuncSetAttribute(k_gru, cudaFuncAttributeMaxDynamicSharedMemorySize, K2_SMEM);

    k_prep_gru<<<(416 * 384 + 255) / 256, 256>>>(wih0, whh0, wih1, whh1);
    k_prep_cust<<<(FEAT * CH + CH * COUT + 255) / 256, 256>>>(cust_w1, cust_w2);
    k_cust<<<NROWS / K1_ROWS, 256>>>(customers, cust_b1, cust_b2);
    k_gru<<<NSEQ / STILE, 512, K2_SMEM>>>(bih0, bhh0, bih1, bhh1);
    k_final<<<BATCH, 128>>>(candidates, cand_w, cand_b,
                            fc1w, fc1b, fc2w, fc2b, fc3w, fc3b,
                            (float*)d_out);
}